// round 5
// baseline (speedup 1.0000x reference)
#include <cuda_runtime.h>
#include <cstdint>

// ---------------- scratch (device globals) ----------------------------------
#define MAXN 50176  // padded 50000 (multiple of 128)
__device__ float g_agg[MAXN * 128];
__device__ float g_h  [MAXN * 128];
__device__ float g_pool[256 * 128];
__device__ float g_cnt [256];
// per weight matrix: [chunk(2)][hi 8192 | lo 8192] floats, B-fragment layout
__device__ float g_wimg[4 * 32768];

// ---------------- helpers ----------------------------------------------------
__device__ __forceinline__ void split1(float x, float& h, float& l) {
    uint32_t hb; asm("cvt.rna.tf32.f32 %0, %1;" : "=r"(hb) : "f"(x));
    h = __uint_as_float(hb);
    float r = x - h;
    uint32_t lb; asm("cvt.rna.tf32.f32 %0, %1;" : "=r"(lb) : "f"(r));
    l = __uint_as_float(lb);
}

__device__ __forceinline__ void mma8(float* d, uint32_t a0, uint32_t a1, uint32_t a2,
                                     uint32_t a3, uint32_t b0, uint32_t b1) {
    asm volatile("mma.sync.aligned.m16n8k8.row.col.f32.tf32.tf32.f32 "
                 "{%0,%1,%2,%3}, {%4,%5,%6,%7}, {%8,%9}, {%0,%1,%2,%3};"
                 : "+f"(d[0]), "+f"(d[1]), "+f"(d[2]), "+f"(d[3])
                 : "r"(a0), "r"(a1), "r"(a2), "r"(a3), "r"(b0), "r"(b1));
}

// ---------------- zero / copy ------------------------------------------------
__global__ void zero_kernel(float* __restrict__ p, int n4) {
    int i = blockIdx.x * blockDim.x + threadIdx.x;
    if (i < n4) ((float4*)p)[i] = make_float4(0.f, 0.f, 0.f, 0.f);
}
__global__ void copy_kernel(const float* __restrict__ s, float* __restrict__ d, int n4) {
    int i = blockIdx.x * blockDim.x + threadIdx.x;
    if (i < n4) ((float4*)d)[i] = ((const float4*)s)[i];
}

// ---------------- weight image prep: split + B-fragment layout ---------------
// W: [128 k][128 n] row-major. Per chunk c (64 k), B-frag idx for (k,n):
//   ks=(k&63)>>3, kr=k&7, tg=kr&3, slot=kr>>2, g=n&7, nt=n>>3, lane=g*4+tg
//   fi = ((nt*8+ks)*32+lane)*2 + slot
__global__ void prep_w_kernel(const float* __restrict__ W, float* __restrict__ img) {
    int i = blockIdx.x * blockDim.x + threadIdx.x;
    if (i >= 16384) return;
    int k = i >> 7, n = i & 127;
    float h, l; split1(__ldg(W + k * 128 + n), h, l);
    int c = k >> 6, kk = k & 63;
    int ks = kk >> 3, kr = kk & 7;
    uint32_t fi = (uint32_t)((((n >> 3) * 8 + ks) * 32 + (n & 7) * 4 + (kr & 3)) * 2 + (kr >> 2));
    img[c * 16384 + fi]        = h;
    img[c * 16384 + 8192 + fi] = l;
}

// ---------------- edge scatter-add: agg[dst] += X[src] ----------------------
__global__ void scatter_kernel(const float* __restrict__ X,
                               const int* __restrict__ src,
                               const int* __restrict__ dst,
                               float* __restrict__ agg, int E) {
    int warp = (blockIdx.x * blockDim.x + threadIdx.x) >> 5;
    int lane = threadIdx.x & 31;
    if (warp >= E) return;
    int s = __ldg(src + warp);
    int d = __ldg(dst + warp);
    float4 v = __ldg(((const float4*)(X + (size_t)s * 128)) + lane);
    float* p = agg + (size_t)d * 128 + lane * 4;
    asm volatile("red.global.add.v4.f32 [%0], {%1, %2, %3, %4};"
                 :: "l"(p), "f"(v.x), "f"(v.y), "f"(v.z), "f"(v.w) : "memory");
}

// ---------------- fused MLP: OUT = relu(A@Wa+ba)@Wb+bb on tf32 mma.sync ------
// smem floats: Ah[16384] Al[16384] Wh[8192] Wl[8192]  (192 KB)
#define SM_TOT (49152 * 4)

// A-frag index for (row r 0..127, k kk 0..127):
//   mt=r>>4, rr=r&15, g=rr&7, h8=rr>>3, ks=kk>>3, kr=kk&7, t=kr&3, th=kr>>2
//   lane=g*4+t, slot=h8+2*th, idx=((mt*16+ks)*32+lane)*4+slot
__device__ __forceinline__ int afrag_idx(int mt, int ks, int lane, int slot) {
    return ((mt * 16 + ks) * 32 + lane) * 4 + slot;
}

__device__ __forceinline__ void do_chunk(const float* __restrict__ Ah,
                                         const float* __restrict__ Al,
                                         const float* __restrict__ Wh,
                                         const float* __restrict__ Wlo,
                                         int wm, int wn, int lane, int c,
                                         float acc[4][4][4]) {
#pragma unroll
    for (int ks = 0; ks < 8; ks++) {
        const int ksA = c * 8 + ks;
        uint32_t ah[4][4], al[4][4];
#pragma unroll
        for (int mt = 0; mt < 4; mt++) {
            float4 h4 = *(const float4*)&Ah[afrag_idx(wm * 4 + mt, ksA, lane, 0)];
            float4 l4 = *(const float4*)&Al[afrag_idx(wm * 4 + mt, ksA, lane, 0)];
            ah[mt][0] = __float_as_uint(h4.x); ah[mt][1] = __float_as_uint(h4.y);
            ah[mt][2] = __float_as_uint(h4.z); ah[mt][3] = __float_as_uint(h4.w);
            al[mt][0] = __float_as_uint(l4.x); al[mt][1] = __float_as_uint(l4.y);
            al[mt][2] = __float_as_uint(l4.z); al[mt][3] = __float_as_uint(l4.w);
        }
        uint32_t bh[4][2], bl[4][2];
#pragma unroll
        for (int nt = 0; nt < 4; nt++) {
            int bi = (((wn * 4 + nt) * 8 + ks) * 32 + lane) * 2;
            float2 h2 = *(const float2*)&Wh[bi];
            float2 l2 = *(const float2*)&Wlo[bi];
            bh[nt][0] = __float_as_uint(h2.x); bh[nt][1] = __float_as_uint(h2.y);
            bl[nt][0] = __float_as_uint(l2.x); bl[nt][1] = __float_as_uint(l2.y);
        }
#pragma unroll
        for (int mt = 0; mt < 4; mt++)
#pragma unroll
            for (int nt = 0; nt < 4; nt++) {
                mma8(acc[mt][nt], ah[mt][0], ah[mt][1], ah[mt][2], ah[mt][3],
                     bh[nt][0], bh[nt][1]);
                mma8(acc[mt][nt], ah[mt][0], ah[mt][1], ah[mt][2], ah[mt][3],
                     bl[nt][0], bl[nt][1]);
                mma8(acc[mt][nt], al[mt][0], al[mt][1], al[mt][2], al[mt][3],
                     bh[nt][0], bh[nt][1]);
            }
    }
}

__global__ __launch_bounds__(256)
void fused_mlp_kernel(const float* __restrict__ A,
                      const float* __restrict__ imgA, const float* __restrict__ ba,
                      const float* __restrict__ imgB, const float* __restrict__ bb,
                      float* __restrict__ OUT, int M) {
    extern __shared__ float sm[];
    float* Ah  = sm;
    float* Al  = sm + 16384;
    float* Wh  = sm + 32768;
    float* Wlo = sm + 40960;

    const int tid = threadIdx.x, wid = tid >> 5, lane = tid & 31;
    const int wm = wid >> 2, wn = wid & 3;
    const int g = lane >> 2, tg = lane & 3;
    const int row0 = blockIdx.x * 128;

    float acc[4][4][4];
#pragma unroll
    for (int a = 0; a < 4; a++)
#pragma unroll
        for (int b = 0; b < 4; b++)
#pragma unroll
            for (int e = 0; e < 4; e++) acc[a][b][e] = 0.f;

    // ---- stage A (full 128x128, hi/lo split, frag layout) ----
    for (int i = tid; i < 4096; i += 256) {
        int r = i >> 5, q = i & 31, kk = q * 4;
        float4 v = __ldg(((const float4*)(A + (size_t)(row0 + r) * 128)) + q);
        int mt = r >> 4, rr = r & 15, gg = rr & 7, h8 = rr >> 3;
        int ks = kk >> 3, th = (kk & 7) >> 2;
        int slot = h8 + 2 * th;
        int base = ((mt * 16 + ks) * 32 + gg * 4) * 4 + slot;
        float hv, lv;
        split1(v.x, hv, lv); Ah[base +  0] = hv; Al[base +  0] = lv;
        split1(v.y, hv, lv); Ah[base +  4] = hv; Al[base +  4] = lv;
        split1(v.z, hv, lv); Ah[base +  8] = hv; Al[base +  8] = lv;
        split1(v.w, hv, lv); Ah[base + 12] = hv; Al[base + 12] = lv;
    }
    // ---- GEMM1 over 2 K-chunks ----
    for (int c = 0; c < 2; c++) {
        const float4* s0 = (const float4*)(imgA + c * 16384);
        const float4* s1 = (const float4*)(imgA + c * 16384 + 8192);
        for (int i = tid; i < 2048; i += 256) {
            ((float4*)Wh)[i]  = __ldg(s0 + i);
            ((float4*)Wlo)[i] = __ldg(s1 + i);
        }
        __syncthreads();
        do_chunk(Ah, Al, Wh, Wlo, wm, wn, lane, c, acc);
        __syncthreads();
    }

    // ---- epilogue1: bias+relu+split -> H frags back into Ah/Al ----
#pragma unroll
    for (int mt = 0; mt < 4; mt++)
#pragma unroll
        for (int nt = 0; nt < 4; nt++) {
            int colb = wn * 32 + nt * 8 + tg * 2;
            float b0 = __ldg(ba + colb), b1 = __ldg(ba + colb + 1);
#pragma unroll
            for (int e = 0; e < 4; e++) {
                float v = fmaxf(acc[mt][nt][e] + ((e & 1) ? b1 : b0), 0.f);
                float hv, lv; split1(v, hv, lv);
                int mtd = wm * 4 + mt;
                int ksd = wn * 4 + nt;
                int kr = tg * 2 + (e & 1);
                int laned = g * 4 + (kr & 3);
                int slot = (e >> 1) + 2 * (kr >> 2);
                int idx = ((mtd * 16 + ksd) * 32 + laned) * 4 + slot;
                Ah[idx] = hv; Al[idx] = lv;
                acc[mt][nt][e] = 0.f;
            }
        }
    __syncthreads();

    // ---- GEMM2 over 2 K-chunks ----
    for (int c = 0; c < 2; c++) {
        const float4* s0 = (const float4*)(imgB + c * 16384);
        const float4* s1 = (const float4*)(imgB + c * 16384 + 8192);
        for (int i = tid; i < 2048; i += 256) {
            ((float4*)Wh)[i]  = __ldg(s0 + i);
            ((float4*)Wlo)[i] = __ldg(s1 + i);
        }
        __syncthreads();
        do_chunk(Ah, Al, Wh, Wlo, wm, wn, lane, c, acc);
        __syncthreads();
    }

    // ---- epilogue2: OUT = D2 + bb ----
#pragma unroll
    for (int mt = 0; mt < 4; mt++) {
#pragma unroll
        for (int e2 = 0; e2 < 2; e2++) {  // row-half: c0/c1 vs c2/c3
            int row = row0 + wm * 64 + mt * 16 + g + e2 * 8;
            if (row < M) {
                float* orow = OUT + (size_t)row * 128;
#pragma unroll
                for (int nt = 0; nt < 4; nt++) {
                    int colb = wn * 32 + nt * 8 + tg * 2;
                    float2 o;
                    o.x = acc[mt][nt][e2 * 2 + 0] + __ldg(bb + colb);
                    o.y = acc[mt][nt][e2 * 2 + 1] + __ldg(bb + colb + 1);
                    *(float2*)(orow + colb) = o;
                }
            }
        }
    }
}

// ---------------- mean-pool accumulate --------------------------------------
__global__ void pool_kernel(const float* __restrict__ H, const int* __restrict__ batch,
                            float* __restrict__ sums, float* __restrict__ cnt, int N) {
    int node = (blockIdx.x * blockDim.x + threadIdx.x) >> 5;
    int lane = threadIdx.x & 31;
    if (node >= N) return;
    int g = __ldg(batch + node);
    float4 v = __ldg(((const float4*)(H + (size_t)node * 128)) + lane);
    float* p = sums + (size_t)g * 128 + lane * 4;
    asm volatile("red.global.add.v4.f32 [%0], {%1, %2, %3, %4};"
                 :: "l"(p), "f"(v.x), "f"(v.y), "f"(v.z), "f"(v.w) : "memory");
    if (lane == 0) atomicAdd(cnt + g, 1.0f);
}

// ---------------- head: out = (sums/cnt) @ Wl + bl --------------------------
__global__ void final_kernel(const float* __restrict__ sums, const float* __restrict__ cnt,
                             const float* __restrict__ Wl, const float* __restrict__ bl,
                             float* __restrict__ out) {
    int g = blockIdx.x;
    int o = threadIdx.x;  // 64 threads
    __shared__ float p[128];
    float c = fmaxf(__ldg(cnt + g), 1.0f);
    for (int k = threadIdx.x; k < 128; k += 64)
        p[k] = __ldg(sums + g * 128 + k) / c;
    __syncthreads();
    float acc = __ldg(bl + o);
#pragma unroll 16
    for (int k = 0; k < 128; k++)
        acc += p[k] * __ldg(Wl + k * 64 + o);
    out[g * 64 + o] = acc;
}

// ---------------- launch -----------------------------------------------------
extern "C" void kernel_launch(void* const* d_in, const int* in_sizes, int n_in,
                              void* d_out, int out_size) {
    const float* x     = (const float*)d_in[0];
    const int*   ei    = (const int*)  d_in[1];
    const int*   batch = (const int*)  d_in[2];
    const float* W1a = (const float*)d_in[3];
    const float* b1a = (const float*)d_in[4];
    const float* W1b = (const float*)d_in[5];
    const float* b1b = (const float*)d_in[6];
    const float* W2a = (const float*)d_in[7];
    const float* b2a = (const float*)d_in[8];
    const float* W2b = (const float*)d_in[9];
    const float* b2b = (const float*)d_in[10];
    const float* Wl  = (const float*)d_in[11];
    const float* bl  = (const float*)d_in[12];
    float* out = (float*)d_out;

    const int N = in_sizes[0] / 128;
    const int E = in_sizes[1] / 2;
    const int* src = ei;
    const int* dst = ei + E;

    float *agg, *h, *pool, *cnt, *wimg;
    cudaGetSymbolAddress((void**)&agg,  g_agg);
    cudaGetSymbolAddress((void**)&h,    g_h);
    cudaGetSymbolAddress((void**)&pool, g_pool);
    cudaGetSymbolAddress((void**)&cnt,  g_cnt);
    cudaGetSymbolAddress((void**)&wimg, g_wimg);

    cudaFuncSetAttribute(fused_mlp_kernel,
                         cudaFuncAttributeMaxDynamicSharedMemorySize, SM_TOT);

    const int n4      = N * 32;
    const int cblocks = (n4 + 255) / 256;
    const int eblocks = (E + 7) / 8;
    const int gblocks = (N + 127) / 128;   // 391
    const int pblocks = (N + 7) / 8;

    // weight images (tf32 split + fragment layout), once per launch
    prep_w_kernel<<<64, 256>>>(W1a, wimg + 0 * 32768);
    prep_w_kernel<<<64, 256>>>(W1b, wimg + 1 * 32768);
    prep_w_kernel<<<64, 256>>>(W2a, wimg + 2 * 32768);
    prep_w_kernel<<<64, 256>>>(W2b, wimg + 3 * 32768);

    // ---- layer 1: agg = x + sum_j x_j; h = MLP1(agg) ----
    copy_kernel   <<<cblocks, 256>>>(x, agg, n4);
    scatter_kernel<<<eblocks, 256>>>(x, src, dst, agg, E);
    fused_mlp_kernel<<<gblocks, 256, SM_TOT>>>(agg, wimg + 0 * 32768, b1a,
                                               wimg + 1 * 32768, b1b, h, N);

    // ---- layer 2 ----
    copy_kernel   <<<cblocks, 256>>>(h, agg, n4);
    scatter_kernel<<<eblocks, 256>>>(h, src, dst, agg, E);
    fused_mlp_kernel<<<gblocks, 256, SM_TOT>>>(agg, wimg + 2 * 32768, b2a,
                                               wimg + 3 * 32768, b2b, h, N);

    // ---- pool + head ----
    zero_kernel <<<32, 256>>>(pool, 256 * 128 / 4);
    zero_kernel <<<1,  64>>>(cnt, 64);
    pool_kernel <<<pblocks, 256>>>(h, batch, pool, cnt, N);
    final_kernel<<<256, 64>>>(pool, cnt, Wl, bl, out);
}

// round 6
// speedup vs baseline: 1.0735x; 1.0735x over previous
#include <cuda_runtime.h>
#include <cstdint>

// ---------------- scratch (device globals) ----------------------------------
#define MAXN 50176   // padded 50000 (multiple of 128)
#define MAXE 1048576
__device__ float g_agg[MAXN * 128];
__device__ float g_t  [MAXN * 128];
__device__ float g_h  [MAXN * 128];
__device__ float g_pool[256 * 128];
__device__ float g_cnt [256];
__device__ int   g_deg [MAXN];
__device__ int   g_off [MAXN];
__device__ int   g_cur [MAXN];
__device__ int   g_adj [MAXE];

// ---------------- zero -------------------------------------------------------
__global__ void zero_kernel(float* __restrict__ p, int n4) {
    int i = blockIdx.x * blockDim.x + threadIdx.x;
    if (i < n4) ((float4*)p)[i] = make_float4(0.f, 0.f, 0.f, 0.f);
}

// ---------------- CSR build --------------------------------------------------
__global__ void count_kernel(const int* __restrict__ dst, int* __restrict__ deg, int E) {
    int e = blockIdx.x * blockDim.x + threadIdx.x;
    if (e < E) atomicAdd(deg + __ldg(dst + e), 1);
}

// single-block exclusive scan over deg -> off (and cursor copy)
__global__ void scan_kernel(const int* __restrict__ deg, int* __restrict__ off,
                            int* __restrict__ cur, int N) {
    __shared__ int part[1024];
    const int tid = threadIdx.x;
    const int seg = (N + 1023) / 1024;
    const int start = tid * seg;
    const int end = min(start + seg, N);
    int s = 0;
    for (int i = start; i < end; i++) s += deg[i];
    part[tid] = s;
    __syncthreads();
    int v = s;
#pragma unroll
    for (int d = 1; d < 1024; d <<= 1) {
        int t = (tid >= d) ? part[tid - d] : 0;
        __syncthreads();
        part[tid] += t;
        __syncthreads();
    }
    int run = part[tid] - v;  // exclusive prefix of this segment
    for (int i = start; i < end; i++) {
        off[i] = run; cur[i] = run;
        run += deg[i];
    }
}

__global__ void fill_kernel(const int* __restrict__ src, const int* __restrict__ dst,
                            int* __restrict__ cur, int* __restrict__ adj, int E) {
    int e = blockIdx.x * blockDim.x + threadIdx.x;
    if (e < E) {
        int p = atomicAdd(cur + __ldg(dst + e), 1);
        adj[p] = __ldg(src + e);
    }
}

// ---------------- gather: agg[i] = X[i] + sum_{j in adj(i)} X[j] -------------
__global__ void gather_kernel(const float* __restrict__ X,
                              const int* __restrict__ adj,
                              const int* __restrict__ off,
                              const int* __restrict__ deg,
                              float* __restrict__ agg, int N) {
    int node = (blockIdx.x * blockDim.x + threadIdx.x) >> 5;
    int lane = threadIdx.x & 31;
    if (node >= N) return;
    float4 a0 = __ldg(((const float4*)(X + (size_t)node * 128)) + lane);
    float4 a1 = make_float4(0.f, 0.f, 0.f, 0.f);
    float4 a2 = make_float4(0.f, 0.f, 0.f, 0.f);
    float4 a3 = make_float4(0.f, 0.f, 0.f, 0.f);
    const int start = __ldg(off + node);
    const int d = __ldg(deg + node);
    int j = 0;
    for (; j + 4 <= d; j += 4) {
        int n0 = __ldg(adj + start + j);
        int n1 = __ldg(adj + start + j + 1);
        int n2 = __ldg(adj + start + j + 2);
        int n3 = __ldg(adj + start + j + 3);
        float4 v0 = __ldg(((const float4*)(X + (size_t)n0 * 128)) + lane);
        float4 v1 = __ldg(((const float4*)(X + (size_t)n1 * 128)) + lane);
        float4 v2 = __ldg(((const float4*)(X + (size_t)n2 * 128)) + lane);
        float4 v3 = __ldg(((const float4*)(X + (size_t)n3 * 128)) + lane);
        a0.x += v0.x; a0.y += v0.y; a0.z += v0.z; a0.w += v0.w;
        a1.x += v1.x; a1.y += v1.y; a1.z += v1.z; a1.w += v1.w;
        a2.x += v2.x; a2.y += v2.y; a2.z += v2.z; a2.w += v2.w;
        a3.x += v3.x; a3.y += v3.y; a3.z += v3.z; a3.w += v3.w;
    }
    for (; j < d; j++) {
        int n0 = __ldg(adj + start + j);
        float4 v0 = __ldg(((const float4*)(X + (size_t)n0 * 128)) + lane);
        a0.x += v0.x; a0.y += v0.y; a0.z += v0.z; a0.w += v0.w;
    }
    a0.x += a1.x + a2.x + a3.x;
    a0.y += a1.y + a2.y + a3.y;
    a0.z += a1.z + a2.z + a3.z;
    a0.w += a1.w + a2.w + a3.w;
    ((float4*)(agg + (size_t)node * 128))[lane] = a0;
}

// ---------------- SGEMM via packed f32x2: C = act(A @ W + bias) -------------
#define TK 16

__global__ __launch_bounds__(256, 2)
void gemm128_kernel(const float* __restrict__ A, const float* __restrict__ W,
                    const float* __restrict__ bias, float* __restrict__ C,
                    int M, int do_relu) {
    __shared__ float As[2][128][TK];
    __shared__ float Ws[2][TK][128];
    const int tid  = threadIdx.x;
    const int row0 = blockIdx.x * 128;
    const int tx = tid & 15, ty = tid >> 4;
    const int rrow = ty * 8, ccol = tx * 8;

    unsigned long long acc[8][4];
#pragma unroll
    for (int i = 0; i < 8; i++)
#pragma unroll
        for (int j = 0; j < 4; j++) acc[i][j] = 0ull;

#define STAGE(K0, BUF) do {                                                     \
        _Pragma("unroll")                                                       \
        for (int t = 0; t < 2; t++) {                                           \
            int ch = tid + t * 256;                                             \
            int r = ch >> 2, c = ch & 3;                                        \
            const float* g = A + (size_t)(row0 + r) * 128 + (K0) + c * 4;       \
            unsigned sm = (unsigned)__cvta_generic_to_shared(&As[BUF][r][c*4]); \
            asm volatile("cp.async.cg.shared.global [%0], [%1], 16;"            \
                         :: "r"(sm), "l"(g));                                   \
        }                                                                       \
        _Pragma("unroll")                                                       \
        for (int t = 0; t < 2; t++) {                                           \
            int ch = tid + t * 256;                                             \
            int r = ch >> 5, c = ch & 31;                                       \
            const float* g = W + (size_t)((K0) + r) * 128 + c * 4;              \
            unsigned sm = (unsigned)__cvta_generic_to_shared(&Ws[BUF][r][c*4]); \
            asm volatile("cp.async.cg.shared.global [%0], [%1], 16;"            \
                         :: "r"(sm), "l"(g));                                   \
        }                                                                       \
        asm volatile("cp.async.commit_group;");                                 \
    } while (0)

    STAGE(0, 0);

    for (int s = 0; s < 128 / TK; s++) {
        if (s < 128 / TK - 1) {
            STAGE((s + 1) * TK, (s + 1) & 1);
            asm volatile("cp.async.wait_group 1;");
        } else {
            asm volatile("cp.async.wait_group 0;");
        }
        __syncthreads();

        const int b = s & 1;
#pragma unroll
        for (int k4 = 0; k4 < TK / 4; k4++) {
            float4 av[8];
#pragma unroll
            for (int i = 0; i < 8; i++)
                av[i] = *(const float4*)&As[b][rrow + i][k4 * 4];
#pragma unroll
            for (int kk = 0; kk < 4; kk++) {
                int k = k4 * 4 + kk;
                ulonglong2 w01 = *(const ulonglong2*)&Ws[b][k][ccol];
                ulonglong2 w23 = *(const ulonglong2*)&Ws[b][k][ccol + 4];
#pragma unroll
                for (int i = 0; i < 8; i++) {
                    float a = (kk == 0) ? av[i].x : (kk == 1) ? av[i].y
                            : (kk == 2) ? av[i].z : av[i].w;
                    unsigned long long a2;
                    asm("mov.b64 %0, {%1, %1};" : "=l"(a2) : "f"(a));
                    asm("fma.rn.f32x2 %0, %1, %2, %0;"
                        : "+l"(acc[i][0]) : "l"(a2), "l"(w01.x));
                    asm("fma.rn.f32x2 %0, %1, %2, %0;"
                        : "+l"(acc[i][1]) : "l"(a2), "l"(w01.y));
                    asm("fma.rn.f32x2 %0, %1, %2, %0;"
                        : "+l"(acc[i][2]) : "l"(a2), "l"(w23.x));
                    asm("fma.rn.f32x2 %0, %1, %2, %0;"
                        : "+l"(acc[i][3]) : "l"(a2), "l"(w23.y));
                }
            }
        }
        __syncthreads();
    }

    float4 bv0 = __ldg((const float4*)(bias + ccol));
    float4 bv1 = __ldg((const float4*)(bias + ccol + 4));
    float bb[8] = {bv0.x, bv0.y, bv0.z, bv0.w, bv1.x, bv1.y, bv1.z, bv1.w};
#pragma unroll
    for (int i = 0; i < 8; i++) {
        int grow = row0 + rrow + i;
        if (grow < M) {
            float o[8];
#pragma unroll
            for (int j = 0; j < 4; j++) {
                float lo, hi;
                asm("mov.b64 {%0, %1}, %2;" : "=f"(lo), "=f"(hi) : "l"(acc[i][j]));
                o[2 * j]     = lo + bb[2 * j];
                o[2 * j + 1] = hi + bb[2 * j + 1];
            }
            if (do_relu)
#pragma unroll
                for (int j = 0; j < 8; j++) o[j] = fmaxf(o[j], 0.f);
            *(float4*)(C + (size_t)grow * 128 + ccol)     = make_float4(o[0], o[1], o[2], o[3]);
            *(float4*)(C + (size_t)grow * 128 + ccol + 4) = make_float4(o[4], o[5], o[6], o[7]);
        }
    }
}

// ---------------- mean-pool accumulate --------------------------------------
__global__ void pool_kernel(const float* __restrict__ H, const int* __restrict__ batch,
                            float* __restrict__ sums, float* __restrict__ cnt, int N) {
    int node = (blockIdx.x * blockDim.x + threadIdx.x) >> 5;
    int lane = threadIdx.x & 31;
    if (node >= N) return;
    int g = __ldg(batch + node);
    float4 v = __ldg(((const float4*)(H + (size_t)node * 128)) + lane);
    float* p = sums + (size_t)g * 128 + lane * 4;
    asm volatile("red.global.add.v4.f32 [%0], {%1, %2, %3, %4};"
                 :: "l"(p), "f"(v.x), "f"(v.y), "f"(v.z), "f"(v.w) : "memory");
    if (lane == 0) atomicAdd(cnt + g, 1.0f);
}

// ---------------- head: out = (sums/cnt) @ Wl + bl --------------------------
__global__ void final_kernel(const float* __restrict__ sums, const float* __restrict__ cnt,
                             const float* __restrict__ Wl, const float* __restrict__ bl,
                             float* __restrict__ out) {
    int g = blockIdx.x;
    int o = threadIdx.x;  // 64 threads
    __shared__ float p[128];
    float c = fmaxf(__ldg(cnt + g), 1.0f);
    for (int k = threadIdx.x; k < 128; k += 64)
        p[k] = __ldg(sums + g * 128 + k) / c;
    __syncthreads();
    float acc = __ldg(bl + o);
#pragma unroll 16
    for (int k = 0; k < 128; k++)
        acc += p[k] * __ldg(Wl + k * 64 + o);
    out[g * 64 + o] = acc;
}

// ---------------- launch -----------------------------------------------------
extern "C" void kernel_launch(void* const* d_in, const int* in_sizes, int n_in,
                              void* d_out, int out_size) {
    const float* x     = (const float*)d_in[0];
    const int*   ei    = (const int*)  d_in[1];
    const int*   batch = (const int*)  d_in[2];
    const float* W1a = (const float*)d_in[3];
    const float* b1a = (const float*)d_in[4];
    const float* W1b = (const float*)d_in[5];
    const float* b1b = (const float*)d_in[6];
    const float* W2a = (const float*)d_in[7];
    const float* b2a = (const float*)d_in[8];
    const float* W2b = (const float*)d_in[9];
    const float* b2b = (const float*)d_in[10];
    const float* Wl  = (const float*)d_in[11];
    const float* bl  = (const float*)d_in[12];
    float* out = (float*)d_out;

    const int N = in_sizes[0] / 128;
    const int E = in_sizes[1] / 2;
    const int* src = ei;
    const int* dst = ei + E;

    float *agg, *t, *h, *pool, *cnt;
    int *deg, *off, *cur, *adj;
    cudaGetSymbolAddress((void**)&agg,  g_agg);
    cudaGetSymbolAddress((void**)&t,    g_t);
    cudaGetSymbolAddress((void**)&h,    g_h);
    cudaGetSymbolAddress((void**)&pool, g_pool);
    cudaGetSymbolAddress((void**)&cnt,  g_cnt);
    cudaGetSymbolAddress((void**)&deg,  g_deg);
    cudaGetSymbolAddress((void**)&off,  g_off);
    cudaGetSymbolAddress((void**)&cur,  g_cur);
    cudaGetSymbolAddress((void**)&adj,  g_adj);

    const int eblocks = (E + 255) / 256;
    const int gblocks = (N + 127) / 128;        // GEMM tiles
    const int wblocks = (N * 32 + 255) / 256;   // warp-per-node kernels

    // ---- CSR build (once per launch) ----
    zero_kernel <<<(MAXN / 4 + 255) / 256, 256>>>((float*)deg, MAXN / 4);
    count_kernel<<<eblocks, 256>>>(dst, deg, E);
    scan_kernel <<<1, 1024>>>(deg, off, cur, N);
    fill_kernel <<<eblocks, 256>>>(src, dst, cur, adj, E);

    // ---- layer 1: agg = x + sum_j x_j; h = MLP1(agg) ----
    gather_kernel<<<wblocks, 256>>>(x, adj, off, deg, agg, N);
    gemm128_kernel<<<gblocks, 256>>>(agg, W1a, b1a, t, N, 1);
    gemm128_kernel<<<gblocks, 256>>>(t,   W1b, b1b, h, N, 0);

    // ---- layer 2 ----
    gather_kernel<<<wblocks, 256>>>(h, adj, off, deg, agg, N);
    gemm128_kernel<<<gblocks, 256>>>(agg, W2a, b2a, t, N, 1);
    gemm128_kernel<<<gblocks, 256>>>(t,   W2b, b2b, h, N, 0);

    // ---- pool + head ----
    zero_kernel <<<32, 256>>>(pool, 256 * 128 / 4);
    zero_kernel <<<1,  64>>>(cnt, 64);
    pool_kernel <<<wblocks, 256>>>(h, batch, pool, cnt, N);
    final_kernel<<<256, 64>>>(pool, cnt, Wl, bl, out);
}

// round 7
// speedup vs baseline: 1.1113x; 1.0352x over previous
#include <cuda_runtime.h>
#include <cstdint>

// ---------------- scratch (device globals) ----------------------------------
#define MAXN 50176   // padded 50000 (multiple of 128)
#define MAXE 1048576
__device__ float g_h  [MAXN * 128];
__device__ float g_pool[256 * 128];
__device__ float g_cnt [256];
__device__ int   g_deg [MAXN];
__device__ int   g_off [MAXN];
__device__ int   g_cur [MAXN];
__device__ int   g_adj [MAXE];

// ---------------- zero -------------------------------------------------------
__global__ void zero_kernel(float* __restrict__ p, int n4) {
    int i = blockIdx.x * blockDim.x + threadIdx.x;
    if (i < n4) ((float4*)p)[i] = make_float4(0.f, 0.f, 0.f, 0.f);
}

// ---------------- CSR build --------------------------------------------------
__global__ void count_kernel(const int* __restrict__ dst, int* __restrict__ deg, int E) {
    int e = blockIdx.x * blockDim.x + threadIdx.x;
    if (e < E) atomicAdd(deg + __ldg(dst + e), 1);
}

__global__ void scan_kernel(const int* __restrict__ deg, int* __restrict__ off,
                            int* __restrict__ cur, int N) {
    __shared__ int part[1024];
    const int tid = threadIdx.x;
    const int seg = (N + 1023) / 1024;
    const int start = tid * seg;
    const int end = min(start + seg, N);
    int s = 0;
    for (int i = start; i < end; i++) s += deg[i];
    part[tid] = s;
    __syncthreads();
    int v = s;
#pragma unroll
    for (int d = 1; d < 1024; d <<= 1) {
        int t = (tid >= d) ? part[tid - d] : 0;
        __syncthreads();
        part[tid] += t;
        __syncthreads();
    }
    int run = part[tid] - v;
    for (int i = start; i < end; i++) {
        off[i] = run; cur[i] = run;
        run += deg[i];
    }
}

__global__ void fill_kernel(const int* __restrict__ src, const int* __restrict__ dst,
                            int* __restrict__ cur, int* __restrict__ adj, int E) {
    int e = blockIdx.x * blockDim.x + threadIdx.x;
    if (e < E) {
        int p = atomicAdd(cur + __ldg(dst + e), 1);
        adj[p] = __ldg(src + e);
    }
}

__global__ void cnt_kernel(const int* __restrict__ batch, float* __restrict__ cnt, int N) {
    int i = blockIdx.x * blockDim.x + threadIdx.x;
    if (i < N) atomicAdd(cnt + __ldg(batch + i), 1.0f);
}

// ---------------- fused GIN layer --------------------------------------------
// Per CTA (128 rows): Atile = x + sum_neighbors; T = relu(Atile@Wa+ba);
// D = T@Wb+bb; mode0: OUT=D. mode1: red.add D into pool[batch[row]].
#define AS 132                              // Atile row stride (floats), banks spread
#define SMEM_BYTES ((128 * AS + 2 * 16 * 128) * 4)

__device__ __forceinline__ void stage_w(const float* __restrict__ W, float* __restrict__ Wsm,
                                        int k0, int tid) {
#pragma unroll
    for (int t = 0; t < 2; t++) {
        int ch = tid + t * 256;
        int r = ch >> 5, c4 = ch & 31;
        const float* g = W + (size_t)(k0 + r) * 128 + c4 * 4;
        unsigned sm = (unsigned)__cvta_generic_to_shared(Wsm + r * 128 + c4 * 4);
        asm volatile("cp.async.cg.shared.global [%0], [%1], 16;" :: "r"(sm), "l"(g));
    }
    asm volatile("cp.async.commit_group;");
}

__device__ __forceinline__ void gemm_from_atile(const float* __restrict__ Atile,
                                                const float* __restrict__ W,
                                                float* __restrict__ Ws,  // 2 bufs of 16x128
                                                int tid, int rrow, int ccol,
                                                unsigned long long acc[8][4]) {
    stage_w(W, Ws, 0, tid);
    for (int s = 0; s < 8; s++) {
        if (s < 7) {
            stage_w(W, Ws + ((s + 1) & 1) * 2048, (s + 1) * 16, tid);
            asm volatile("cp.async.wait_group 1;");
        } else {
            asm volatile("cp.async.wait_group 0;");
        }
        __syncthreads();
        const float* Wb = Ws + (s & 1) * 2048;
#pragma unroll
        for (int k4l = 0; k4l < 4; k4l++) {
            const int kg = s * 16 + k4l * 4;
            float4 av[8];
#pragma unroll
            for (int i = 0; i < 8; i++)
                av[i] = *(const float4*)&Atile[(rrow + i) * AS + kg];
#pragma unroll
            for (int kk = 0; kk < 4; kk++) {
                const float* wrow = Wb + (k4l * 4 + kk) * 128 + ccol;
                ulonglong2 w01 = *(const ulonglong2*)wrow;
                ulonglong2 w23 = *(const ulonglong2*)(wrow + 4);
#pragma unroll
                for (int i = 0; i < 8; i++) {
                    float a = (kk == 0) ? av[i].x : (kk == 1) ? av[i].y
                            : (kk == 2) ? av[i].z : av[i].w;
                    unsigned long long a2;
                    asm("mov.b64 %0, {%1, %1};" : "=l"(a2) : "f"(a));
                    asm("fma.rn.f32x2 %0, %1, %2, %0;" : "+l"(acc[i][0]) : "l"(a2), "l"(w01.x));
                    asm("fma.rn.f32x2 %0, %1, %2, %0;" : "+l"(acc[i][1]) : "l"(a2), "l"(w01.y));
                    asm("fma.rn.f32x2 %0, %1, %2, %0;" : "+l"(acc[i][2]) : "l"(a2), "l"(w23.x));
                    asm("fma.rn.f32x2 %0, %1, %2, %0;" : "+l"(acc[i][3]) : "l"(a2), "l"(w23.y));
                }
            }
        }
        __syncthreads();
    }
}

__global__ __launch_bounds__(256, 2)
void fused_layer_kernel(const float* __restrict__ X,
                        const int* __restrict__ adj, const int* __restrict__ off,
                        const int* __restrict__ deg,
                        const float* __restrict__ Wa, const float* __restrict__ ba,
                        const float* __restrict__ Wb, const float* __restrict__ bbv,
                        float* __restrict__ OUT,
                        const int* __restrict__ batch, float* __restrict__ pool,
                        int N, int mode) {
    extern __shared__ float sm[];
    float* Atile = sm;                 // 128 * AS
    float* Ws    = sm + 128 * AS;      // 2 * 16 * 128

    const int tid = threadIdx.x, wid = tid >> 5, lane = tid & 31;
    const int tx = tid & 15, ty = tid >> 4;
    const int rrow = ty * 8, ccol = tx * 8;
    const int row0 = blockIdx.x * 128;

    // prefetch Wa chunk 0 while gathering
    stage_w(Wa, Ws, 0, tid);

    // ---- gather phase: Atile[row] = X[node] + sum_{j in adj(node)} X[j] ----
    for (int row = wid; row < 128; row += 8) {
        int node = row0 + row;
        float4 a0 = make_float4(0.f, 0.f, 0.f, 0.f);
        float4 a1 = a0, a2 = a0, a3 = a0;
        if (node < N) {
            a0 = __ldg(((const float4*)(X + (size_t)node * 128)) + lane);
            const int start = __ldg(off + node);
            const int d = __ldg(deg + node);
            int j = 0;
            for (; j + 4 <= d; j += 4) {
                int n0 = __ldg(adj + start + j);
                int n1 = __ldg(adj + start + j + 1);
                int n2 = __ldg(adj + start + j + 2);
                int n3 = __ldg(adj + start + j + 3);
                float4 v0 = __ldg(((const float4*)(X + (size_t)n0 * 128)) + lane);
                float4 v1 = __ldg(((const float4*)(X + (size_t)n1 * 128)) + lane);
                float4 v2 = __ldg(((const float4*)(X + (size_t)n2 * 128)) + lane);
                float4 v3 = __ldg(((const float4*)(X + (size_t)n3 * 128)) + lane);
                a0.x += v0.x; a0.y += v0.y; a0.z += v0.z; a0.w += v0.w;
                a1.x += v1.x; a1.y += v1.y; a1.z += v1.z; a1.w += v1.w;
                a2.x += v2.x; a2.y += v2.y; a2.z += v2.z; a2.w += v2.w;
                a3.x += v3.x; a3.y += v3.y; a3.z += v3.z; a3.w += v3.w;
            }
            for (; j < d; j++) {
                int n0 = __ldg(adj + start + j);
                float4 v0 = __ldg(((const float4*)(X + (size_t)n0 * 128)) + lane);
                a0.x += v0.x; a0.y += v0.y; a0.z += v0.z; a0.w += v0.w;
            }
            a0.x += a1.x + a2.x + a3.x;
            a0.y += a1.y + a2.y + a3.y;
            a0.z += a1.z + a2.z + a3.z;
            a0.w += a1.w + a2.w + a3.w;
        }
        *(float4*)&Atile[row * AS + lane * 4] = a0;
    }

    unsigned long long acc[8][4];
#pragma unroll
    for (int i = 0; i < 8; i++)
#pragma unroll
        for (int j = 0; j < 4; j++) acc[i][j] = 0ull;

    // NOTE: gemm_from_atile issues its own stage of chunk 0 again; the duplicate
    // is harmless (same data) and keeps the helper self-contained.
    __syncthreads();

    // ---- GEMM1 ----
    gemm_from_atile(Atile, Wa, Ws, tid, rrow, ccol, acc);

    // ---- epilogue1: relu+bias -> Atile ----
    {
        float4 bv0 = __ldg((const float4*)(ba + ccol));
        float4 bv1 = __ldg((const float4*)(ba + ccol + 4));
        float bb[8] = {bv0.x, bv0.y, bv0.z, bv0.w, bv1.x, bv1.y, bv1.z, bv1.w};
#pragma unroll
        for (int i = 0; i < 8; i++) {
            float o[8];
#pragma unroll
            for (int j = 0; j < 4; j++) {
                float lo, hi;
                asm("mov.b64 {%0, %1}, %2;" : "=f"(lo), "=f"(hi) : "l"(acc[i][j]));
                o[2 * j]     = fmaxf(lo + bb[2 * j], 0.f);
                o[2 * j + 1] = fmaxf(hi + bb[2 * j + 1], 0.f);
                acc[i][j] = 0ull;
            }
            *(float4*)&Atile[(rrow + i) * AS + ccol]     = make_float4(o[0], o[1], o[2], o[3]);
            *(float4*)&Atile[(rrow + i) * AS + ccol + 4] = make_float4(o[4], o[5], o[6], o[7]);
        }
    }
    __syncthreads();

    // ---- GEMM2 ----
    gemm_from_atile(Atile, Wb, Ws, tid, rrow, ccol, acc);

    // ---- epilogue2 ----
    {
        float4 bv0 = __ldg((const float4*)(bbv + ccol));
        float4 bv1 = __ldg((const float4*)(bbv + ccol + 4));
        float bb[8] = {bv0.x, bv0.y, bv0.z, bv0.w, bv1.x, bv1.y, bv1.z, bv1.w};
#pragma unroll
        for (int i = 0; i < 8; i++) {
            int grow = row0 + rrow + i;
            if (grow < N) {
                float o[8];
#pragma unroll
                for (int j = 0; j < 4; j++) {
                    float lo, hi;
                    asm("mov.b64 {%0, %1}, %2;" : "=f"(lo), "=f"(hi) : "l"(acc[i][j]));
                    o[2 * j]     = lo + bb[2 * j];
                    o[2 * j + 1] = hi + bb[2 * j + 1];
                }
                if (mode == 0) {
                    *(float4*)(OUT + (size_t)grow * 128 + ccol)     = make_float4(o[0], o[1], o[2], o[3]);
                    *(float4*)(OUT + (size_t)grow * 128 + ccol + 4) = make_float4(o[4], o[5], o[6], o[7]);
                } else {
                    int g = __ldg(batch + grow);
                    float* p = pool + (size_t)g * 128 + ccol;
                    asm volatile("red.global.add.v4.f32 [%0], {%1, %2, %3, %4};"
                                 :: "l"(p), "f"(o[0]), "f"(o[1]), "f"(o[2]), "f"(o[3]) : "memory");
                    asm volatile("red.global.add.v4.f32 [%0], {%1, %2, %3, %4};"
                                 :: "l"(p + 4), "f"(o[4]), "f"(o[5]), "f"(o[6]), "f"(o[7]) : "memory");
                }
            }
        }
    }
}

// ---------------- head: out = (sums/cnt) @ Wl + bl --------------------------
__global__ void final_kernel(const float* __restrict__ sums, const float* __restrict__ cnt,
                             const float* __restrict__ Wl, const float* __restrict__ bl,
                             float* __restrict__ out) {
    int g = blockIdx.x;
    int o = threadIdx.x;  // 64 threads
    __shared__ float p[128];
    float c = fmaxf(__ldg(cnt + g), 1.0f);
    for (int k = threadIdx.x; k < 128; k += 64)
        p[k] = __ldg(sums + g * 128 + k) / c;
    __syncthreads();
    float acc = __ldg(bl + o);
#pragma unroll 16
    for (int k = 0; k < 128; k++)
        acc += p[k] * __ldg(Wl + k * 64 + o);
    out[g * 64 + o] = acc;
}

// ---------------- launch -----------------------------------------------------
extern "C" void kernel_launch(void* const* d_in, const int* in_sizes, int n_in,
                              void* d_out, int out_size) {
    const float* x     = (const float*)d_in[0];
    const int*   ei    = (const int*)  d_in[1];
    const int*   batch = (const int*)  d_in[2];
    const float* W1a = (const float*)d_in[3];
    const float* b1a = (const float*)d_in[4];
    const float* W1b = (const float*)d_in[5];
    const float* b1b = (const float*)d_in[6];
    const float* W2a = (const float*)d_in[7];
    const float* b2a = (const float*)d_in[8];
    const float* W2b = (const float*)d_in[9];
    const float* b2b = (const float*)d_in[10];
    const float* Wl  = (const float*)d_in[11];
    const float* bl  = (const float*)d_in[12];
    float* out = (float*)d_out;

    const int N = in_sizes[0] / 128;
    const int E = in_sizes[1] / 2;
    const int* src = ei;
    const int* dst = ei + E;

    float *h, *pool, *cnt;
    int *deg, *off, *cur, *adj;
    cudaGetSymbolAddress((void**)&h,    g_h);
    cudaGetSymbolAddress((void**)&pool, g_pool);
    cudaGetSymbolAddress((void**)&cnt,  g_cnt);
    cudaGetSymbolAddress((void**)&deg,  g_deg);
    cudaGetSymbolAddress((void**)&off,  g_off);
    cudaGetSymbolAddress((void**)&cur,  g_cur);
    cudaGetSymbolAddress((void**)&adj,  g_adj);

    cudaFuncSetAttribute(fused_layer_kernel,
                         cudaFuncAttributeMaxDynamicSharedMemorySize, SMEM_BYTES);

    const int eblocks = (E + 255) / 256;
    const int gblocks = (N + 127) / 128;        // 391
    const int nblocks = (N + 255) / 256;

    // ---- CSR build (once per launch) ----
    zero_kernel <<<(MAXN / 4 + 255) / 256, 256>>>((float*)deg, MAXN / 4);
    count_kernel<<<eblocks, 256>>>(dst, deg, E);
    scan_kernel <<<1, 1024>>>(deg, off, cur, N);
    fill_kernel <<<eblocks, 256>>>(src, dst, cur, adj, E);

    // ---- pool init + counts (independent of layers) ----
    zero_kernel<<<32, 256>>>(pool, 256 * 128 / 4);
    zero_kernel<<<1,  64>>>(cnt, 64);
    cnt_kernel <<<nblocks, 256>>>(batch, cnt, N);

    // ---- layer 1: h = MLP1(x + gather) ----
    fused_layer_kernel<<<gblocks, 256, SMEM_BYTES>>>(
        x, adj, off, deg, W1a, b1a, W1b, b1b, h, batch, pool, N, 0);

    // ---- layer 2: pool += MLP2(h + gather), fused ----
    fused_layer_kernel<<<gblocks, 256, SMEM_BYTES>>>(
        h, adj, off, deg, W2a, b2a, W2b, b2b, nullptr, batch, pool, N, 1);

    // ---- head ----
    final_kernel<<<256, 64>>>(pool, cnt, Wl, bl, out);
}

// round 8
// speedup vs baseline: 1.1494x; 1.0343x over previous
#include <cuda_runtime.h>
#include <cstdint>

// ---------------- scratch (device globals) ----------------------------------
#define MAXN 50176   // padded 50000 (multiple of 128)
#define MAXE 1048576
__device__ float g_h  [MAXN * 128];
__device__ float g_pool[256 * 128];
__device__ float g_cnt [256];
__device__ int   g_deg [MAXN];
__device__ int   g_off [MAXN];
__device__ int   g_cur [MAXN];
__device__ int   g_adj [MAXE];

// ---------------- zero -------------------------------------------------------
__global__ void zero_kernel(float* __restrict__ p, int n4) {
    int i = blockIdx.x * blockDim.x + threadIdx.x;
    if (i < n4) ((float4*)p)[i] = make_float4(0.f, 0.f, 0.f, 0.f);
}

// ---------------- CSR build --------------------------------------------------
__global__ void count_kernel(const int* __restrict__ dst, int* __restrict__ deg, int E) {
    int e = blockIdx.x * blockDim.x + threadIdx.x;
    if (e < E) atomicAdd(deg + __ldg(dst + e), 1);
}

__global__ void scan_kernel(const int* __restrict__ deg, int* __restrict__ off,
                            int* __restrict__ cur, int N) {
    __shared__ int part[1024];
    const int tid = threadIdx.x;
    const int seg = (N + 1023) / 1024;
    const int start = tid * seg;
    const int end = min(start + seg, N);
    int s = 0;
    for (int i = start; i < end; i++) s += deg[i];
    part[tid] = s;
    __syncthreads();
    int v = s;
#pragma unroll
    for (int d = 1; d < 1024; d <<= 1) {
        int t = (tid >= d) ? part[tid - d] : 0;
        __syncthreads();
        part[tid] += t;
        __syncthreads();
    }
    int run = part[tid] - v;
    for (int i = start; i < end; i++) {
        off[i] = run; cur[i] = run;
        run += deg[i];
    }
}

__global__ void fill_kernel(const int* __restrict__ src, const int* __restrict__ dst,
                            int* __restrict__ cur, int* __restrict__ adj, int E) {
    int e = blockIdx.x * blockDim.x + threadIdx.x;
    if (e < E) {
        int p = atomicAdd(cur + __ldg(dst + e), 1);
        adj[p] = __ldg(src + e);
    }
}

__global__ void cnt_kernel(const int* __restrict__ batch, float* __restrict__ cnt, int N) {
    int i = blockIdx.x * blockDim.x + threadIdx.x;
    if (i < N) atomicAdd(cnt + __ldg(batch + i), 1.0f);
}

// ---------------- persistent warp-specialized fused GIN layer ----------------
#define AS 132                 // Atile row stride (floats)
#define NSM 148
#define SMEM_BYTES ((2 * 128 * AS + 2 * 16 * 128) * 4)
#define CONS_BAR() asm volatile("bar.sync 1, 256;" ::: "memory")

__device__ __forceinline__ void stage_w(const float* __restrict__ W, float* __restrict__ Wsm,
                                        int k0, int tid) {
#pragma unroll
    for (int t = 0; t < 2; t++) {
        int ch = tid + t * 256;
        int r = ch >> 5, c4 = ch & 31;
        const float* g = W + (size_t)(k0 + r) * 128 + c4 * 4;
        unsigned sm = (unsigned)__cvta_generic_to_shared(Wsm + r * 128 + c4 * 4);
        asm volatile("cp.async.cg.shared.global [%0], [%1], 16;" :: "r"(sm), "l"(g));
    }
    asm volatile("cp.async.commit_group;");
}

__device__ __forceinline__ void gather_rows(const float* __restrict__ X,
                                            const int* __restrict__ adj,
                                            const int* __restrict__ off,
                                            const int* __restrict__ deg,
                                            float* __restrict__ Abuf,
                                            int row0, int N, int warp, int nwarps, int lane) {
    for (int row = warp; row < 128; row += nwarps) {
        int node = row0 + row;
        float4 a0 = make_float4(0.f, 0.f, 0.f, 0.f);
        float4 a1 = a0, a2 = a0, a3 = a0;
        if (node < N) {
            a0 = __ldg(((const float4*)(X + (size_t)node * 128)) + lane);
            const int start = __ldg(off + node);
            const int d = __ldg(deg + node);
            int j = 0;
            for (; j + 4 <= d; j += 4) {
                int n0 = __ldg(adj + start + j);
                int n1 = __ldg(adj + start + j + 1);
                int n2 = __ldg(adj + start + j + 2);
                int n3 = __ldg(adj + start + j + 3);
                float4 v0 = __ldg(((const float4*)(X + (size_t)n0 * 128)) + lane);
                float4 v1 = __ldg(((const float4*)(X + (size_t)n1 * 128)) + lane);
                float4 v2 = __ldg(((const float4*)(X + (size_t)n2 * 128)) + lane);
                float4 v3 = __ldg(((const float4*)(X + (size_t)n3 * 128)) + lane);
                a0.x += v0.x; a0.y += v0.y; a0.z += v0.z; a0.w += v0.w;
                a1.x += v1.x; a1.y += v1.y; a1.z += v1.z; a1.w += v1.w;
                a2.x += v2.x; a2.y += v2.y; a2.z += v2.z; a2.w += v2.w;
                a3.x += v3.x; a3.y += v3.y; a3.z += v3.z; a3.w += v3.w;
            }
            for (; j < d; j++) {
                int n0 = __ldg(adj + start + j);
                float4 v0 = __ldg(((const float4*)(X + (size_t)n0 * 128)) + lane);
                a0.x += v0.x; a0.y += v0.y; a0.z += v0.z; a0.w += v0.w;
            }
            a0.x += a1.x + a2.x + a3.x;
            a0.y += a1.y + a2.y + a3.y;
            a0.z += a1.z + a2.z + a3.z;
            a0.w += a1.w + a2.w + a3.w;
        }
        *(float4*)&Abuf[row * AS + lane * 4] = a0;
    }
}

__device__ __forceinline__ void gemm_from_atile(const float* __restrict__ Atile,
                                                const float* __restrict__ W,
                                                float* __restrict__ Ws,
                                                int tid, int rrow, int ccol,
                                                unsigned long long acc[8][4]) {
    stage_w(W, Ws, 0, tid);
    for (int s = 0; s < 8; s++) {
        if (s < 7) {
            stage_w(W, Ws + ((s + 1) & 1) * 2048, (s + 1) * 16, tid);
            asm volatile("cp.async.wait_group 1;");
        } else {
            asm volatile("cp.async.wait_group 0;");
        }
        CONS_BAR();
        const float* Wb = Ws + (s & 1) * 2048;
#pragma unroll
        for (int k4l = 0; k4l < 4; k4l++) {
            const int kg = s * 16 + k4l * 4;
            float4 av[8];
#pragma unroll
            for (int i = 0; i < 8; i++)
                av[i] = *(const float4*)&Atile[(rrow + i) * AS + kg];
#pragma unroll
            for (int kk = 0; kk < 4; kk++) {
                const float* wrow = Wb + (k4l * 4 + kk) * 128 + ccol;
                ulonglong2 w01 = *(const ulonglong2*)wrow;
                ulonglong2 w23 = *(const ulonglong2*)(wrow + 4);
#pragma unroll
                for (int i = 0; i < 8; i++) {
                    float a = (kk == 0) ? av[i].x : (kk == 1) ? av[i].y
                            : (kk == 2) ? av[i].z : av[i].w;
                    unsigned long long a2;
                    asm("mov.b64 %0, {%1, %1};" : "=l"(a2) : "f"(a));
                    asm("fma.rn.f32x2 %0, %1, %2, %0;" : "+l"(acc[i][0]) : "l"(a2), "l"(w01.x));
                    asm("fma.rn.f32x2 %0, %1, %2, %0;" : "+l"(acc[i][1]) : "l"(a2), "l"(w01.y));
                    asm("fma.rn.f32x2 %0, %1, %2, %0;" : "+l"(acc[i][2]) : "l"(a2), "l"(w23.x));
                    asm("fma.rn.f32x2 %0, %1, %2, %0;" : "+l"(acc[i][3]) : "l"(a2), "l"(w23.y));
                }
            }
        }
        CONS_BAR();
    }
}

__device__ __forceinline__ void consumer_tile(float* __restrict__ Atile,
                                              float* __restrict__ Ws,
                                              const float* __restrict__ Wa, const float* __restrict__ ba,
                                              const float* __restrict__ Wb, const float* __restrict__ bbv,
                                              float* __restrict__ OUT,
                                              const int* __restrict__ batch, float* __restrict__ pool,
                                              int row0, int N, int mode,
                                              int tid, int rrow, int ccol) {
    unsigned long long acc[8][4];
#pragma unroll
    for (int i = 0; i < 8; i++)
#pragma unroll
        for (int j = 0; j < 4; j++) acc[i][j] = 0ull;

    gemm_from_atile(Atile, Wa, Ws, tid, rrow, ccol, acc);

    {   // epilogue1: relu+bias -> Atile
        float4 bv0 = __ldg((const float4*)(ba + ccol));
        float4 bv1 = __ldg((const float4*)(ba + ccol + 4));
        float bb[8] = {bv0.x, bv0.y, bv0.z, bv0.w, bv1.x, bv1.y, bv1.z, bv1.w};
#pragma unroll
        for (int i = 0; i < 8; i++) {
            float o[8];
#pragma unroll
            for (int j = 0; j < 4; j++) {
                float lo, hi;
                asm("mov.b64 {%0, %1}, %2;" : "=f"(lo), "=f"(hi) : "l"(acc[i][j]));
                o[2 * j]     = fmaxf(lo + bb[2 * j], 0.f);
                o[2 * j + 1] = fmaxf(hi + bb[2 * j + 1], 0.f);
                acc[i][j] = 0ull;
            }
            *(float4*)&Atile[(rrow + i) * AS + ccol]     = make_float4(o[0], o[1], o[2], o[3]);
            *(float4*)&Atile[(rrow + i) * AS + ccol + 4] = make_float4(o[4], o[5], o[6], o[7]);
        }
    }
    CONS_BAR();

    gemm_from_atile(Atile, Wb, Ws, tid, rrow, ccol, acc);

    {   // epilogue2
        float4 bv0 = __ldg((const float4*)(bbv + ccol));
        float4 bv1 = __ldg((const float4*)(bbv + ccol + 4));
        float bb[8] = {bv0.x, bv0.y, bv0.z, bv0.w, bv1.x, bv1.y, bv1.z, bv1.w};
#pragma unroll
        for (int i = 0; i < 8; i++) {
            int grow = row0 + rrow + i;
            if (grow < N) {
                float o[8];
#pragma unroll
                for (int j = 0; j < 4; j++) {
                    float lo, hi;
                    asm("mov.b64 {%0, %1}, %2;" : "=f"(lo), "=f"(hi) : "l"(acc[i][j]));
                    o[2 * j]     = lo + bb[2 * j];
                    o[2 * j + 1] = hi + bb[2 * j + 1];
                }
                if (mode == 0) {
                    *(float4*)(OUT + (size_t)grow * 128 + ccol)     = make_float4(o[0], o[1], o[2], o[3]);
                    *(float4*)(OUT + (size_t)grow * 128 + ccol + 4) = make_float4(o[4], o[5], o[6], o[7]);
                } else {
                    int g = __ldg(batch + grow);
                    float* p = pool + (size_t)g * 128 + ccol;
                    asm volatile("red.global.add.v4.f32 [%0], {%1, %2, %3, %4};"
                                 :: "l"(p), "f"(o[0]), "f"(o[1]), "f"(o[2]), "f"(o[3]) : "memory");
                    asm volatile("red.global.add.v4.f32 [%0], {%1, %2, %3, %4};"
                                 :: "l"(p + 4), "f"(o[4]), "f"(o[5]), "f"(o[6]), "f"(o[7]) : "memory");
                }
            }
        }
    }
}

__global__ __launch_bounds__(512, 1)
void fused_layer_kernel(const float* __restrict__ X,
                        const int* __restrict__ adj, const int* __restrict__ off,
                        const int* __restrict__ deg,
                        const float* __restrict__ Wa, const float* __restrict__ ba,
                        const float* __restrict__ Wb, const float* __restrict__ bbv,
                        float* __restrict__ OUT,
                        const int* __restrict__ batch, float* __restrict__ pool,
                        int N, int mode) {
    extern __shared__ float sm[];
    float* Abuf0 = sm;
    float* Abuf1 = sm + 128 * AS;
    float* Ws    = sm + 2 * 128 * AS;

    const int tid = threadIdx.x, wid = tid >> 5, lane = tid & 31;
    const int bid = blockIdx.x;
    const int ntiles = (N + 127) / 128;
    const int nt = (ntiles - bid + NSM - 1) / NSM;   // tiles for this CTA
    if (nt <= 0) return;

    // consumer geometry (tid 0..255)
    const int tx = tid & 15, ty = (tid & 255) >> 4;
    const int rrow = ty * 8, ccol = tx * 8;

    // prologue: all 16 warps gather tile 0 into buf0
    gather_rows(X, adj, off, deg, Abuf0, bid * 128, N, wid, 16, lane);
    __syncthreads();

    for (int i = 0; i < nt; i++) {
        float* Ab = (i & 1) ? Abuf1 : Abuf0;
        int row0 = (bid + i * NSM) * 128;
        if (tid < 256) {
            consumer_tile(Ab, Ws, Wa, ba, Wb, bbv, OUT, batch, pool,
                          row0, N, mode, tid, rrow, ccol);
        } else {
            if (i + 1 < nt) {
                float* An = (i & 1) ? Abuf0 : Abuf1;
                gather_rows(X, adj, off, deg, An, (bid + (i + 1) * NSM) * 128,
                            N, wid - 8, 8, lane);
            }
        }
        __syncthreads();
    }
}

// ---------------- head: out = (sums/cnt) @ Wl + bl --------------------------
__global__ void final_kernel(const float* __restrict__ sums, const float* __restrict__ cnt,
                             const float* __restrict__ Wl, const float* __restrict__ bl,
                             float* __restrict__ out) {
    int g = blockIdx.x;
    int o = threadIdx.x;  // 64 threads
    __shared__ float p[128];
    float c = fmaxf(__ldg(cnt + g), 1.0f);
    for (int k = threadIdx.x; k < 128; k += 64)
        p[k] = __ldg(sums + g * 128 + k) / c;
    __syncthreads();
    float acc = __ldg(bl + o);
#pragma unroll 16
    for (int k = 0; k < 128; k++)
        acc += p[k] * __ldg(Wl + k * 64 + o);
    out[g * 64 + o] = acc;
}

// ---------------- launch -----------------------------------------------------
extern "C" void kernel_launch(void* const* d_in, const int* in_sizes, int n_in,
                              void* d_out, int out_size) {
    const float* x     = (const float*)d_in[0];
    const int*   ei    = (const int*)  d_in[1];
    const int*   batch = (const int*)  d_in[2];
    const float* W1a = (const float*)d_in[3];
    const float* b1a = (const float*)d_in[4];
    const float* W1b = (const float*)d_in[5];
    const float* b1b = (const float*)d_in[6];
    const float* W2a = (const float*)d_in[7];
    const float* b2a = (const float*)d_in[8];
    const float* W2b = (const float*)d_in[9];
    const float* b2b = (const float*)d_in[10];
    const float* Wl  = (const float*)d_in[11];
    const float* bl  = (const float*)d_in[12];
    float* out = (float*)d_out;

    const int N = in_sizes[0] / 128;
    const int E = in_sizes[1] / 2;
    const int* src = ei;
    const int* dst = ei + E;

    float *h, *pool, *cnt;
    int *deg, *off, *cur, *adj;
    cudaGetSymbolAddress((void**)&h,    g_h);
    cudaGetSymbolAddress((void**)&pool, g_pool);
    cudaGetSymbolAddress((void**)&cnt,  g_cnt);
    cudaGetSymbolAddress((void**)&deg,  g_deg);
    cudaGetSymbolAddress((void**)&off,  g_off);
    cudaGetSymbolAddress((void**)&cur,  g_cur);
    cudaGetSymbolAddress((void**)&adj,  g_adj);

    cudaFuncSetAttribute(fused_layer_kernel,
                         cudaFuncAttributeMaxDynamicSharedMemorySize, SMEM_BYTES);

    const int eblocks = (E + 255) / 256;
    const int nblocks = (N + 255) / 256;

    // ---- CSR build (once per launch) ----
    zero_kernel <<<(MAXN / 4 + 255) / 256, 256>>>((float*)deg, MAXN / 4);
    count_kernel<<<eblocks, 256>>>(dst, deg, E);
    scan_kernel <<<1, 1024>>>(deg, off, cur, N);
    fill_kernel <<<eblocks, 256>>>(src, dst, cur, adj, E);

    // ---- pool init + counts ----
    zero_kernel<<<32, 256>>>(pool, 256 * 128 / 4);
    zero_kernel<<<1,  64>>>(cnt, 64);
    cnt_kernel <<<nblocks, 256>>>(batch, cnt, N);

    // ---- layer 1: h = MLP1(x + gather) ----
    fused_layer_kernel<<<NSM, 512, SMEM_BYTES>>>(
        x, adj, off, deg, W1a, b1a, W1b, b1b, h, batch, pool, N, 0);

    // ---- layer 2: pool += MLP2(h + gather), fused ----
    fused_layer_kernel<<<NSM, 512, SMEM_BYTES>>>(
        h, adj, off, deg, W2a, b2a, W2b, b2b, nullptr, batch, pool, N, 1);

    // ---- head ----
    final_kernel<<<256, 64>>>(pool, cnt, Wl, bl, out);
}